// round 1
// baseline (speedup 1.0000x reference)
#include <cuda_runtime.h>
#include <math.h>

#define CN0 30000
#define CN1 90000
#define CN2 60000
#define D_IN 256
#define D_OUT 128
#define HEADS 4
#define NNZ0 960000
#define NNZ1 180000
#define NNZ2 180000
#define CAP 256

// ---------------- scratch (static device arrays; no allocation) ----------------
__device__ float g_y1[HEADS * CN1 * D_OUT];          // relu(x1 W1 + b1) per head
__device__ float g_y2[HEADS * CN2 * D_OUT];          // relu(x2 W1 + b1) per head
__device__ float g_cat[HEADS * CN0 * 4 * D_OUT];     // [h][row][ xi0 | agg0 | agg1 | agg2 ]
__device__ float g_a1[HEADS * CN0];
__device__ float g_a20[HEADS * CN0];
__device__ float g_a21[HEADS * CN1];
__device__ float g_a22[HEADS * CN2];
__device__ int   g_cnt[3 * CN0];
__device__ int   g_list[3 * CN0 * CAP];

// ---------------- zero counters ----------------
__global__ void zero_cnt_kernel() {
    int i = blockIdx.x * blockDim.x + threadIdx.x;
    if (i < 3 * CN0) g_cnt[i] = 0;
}

// ---------------- GEMM1: y = relu(X @ W1h + b1h); fused a1/a2 dots ----------------
// grid: (rowblocks, level, head), block 256 threads, 64 rows x 128 cols per CTA
__global__ __launch_bounds__(256) void gemm1_kernel(
    const float* __restrict__ x0, const float* __restrict__ x1, const float* __restrict__ x2,
    const float* __restrict__ W1, const float* __restrict__ b1,
    const float* __restrict__ a1w, const float* __restrict__ a1b,
    const float* __restrict__ a2w, const float* __restrict__ a2b)
{
    const int lvl = blockIdx.y;
    const int h   = blockIdx.z;
    const int Nl  = (lvl == 0) ? CN0 : (lvl == 1) ? CN1 : CN2;
    const int row0 = blockIdx.x * 64;
    if (row0 >= Nl) return;

    const float* X = (lvl == 0) ? x0 : (lvl == 1) ? x1 : x2;
    float* out; int ldo;
    if (lvl == 0)      { out = g_cat + (size_t)h * CN0 * 512; ldo = 512; }
    else if (lvl == 1) { out = g_y1  + (size_t)h * CN1 * 128; ldo = 128; }
    else               { out = g_y2  + (size_t)h * CN2 * 128; ldo = 128; }
    const float* Wh = W1 + (size_t)h * D_IN * D_OUT;

    __shared__ float Xs[64][32];
    __shared__ float Ws[32][128];

    const int tid  = threadIdx.x;
    const int lane = tid & 31;
    const int warp = tid >> 5;

    float4 acc[8];
#pragma unroll
    for (int r = 0; r < 8; r++) acc[r] = make_float4(0.f, 0.f, 0.f, 0.f);

    for (int k0 = 0; k0 < D_IN; k0 += 32) {
        // load X tile (64 x 32)
#pragma unroll
        for (int i = 0; i < 2; i++) {
            int f = tid * 2 + i;            // 0..511 float4 slots
            int r = f >> 3, kk = (f & 7) * 4;
            float4 v = make_float4(0.f, 0.f, 0.f, 0.f);
            int gr = row0 + r;
            if (gr < Nl) v = *(const float4*)(X + (size_t)gr * D_IN + k0 + kk);
            *(float4*)&Xs[r][kk] = v;
        }
        // load W tile (32 x 128)
#pragma unroll
        for (int i = 0; i < 4; i++) {
            int f = tid + i * 256;          // 0..1023 float4 slots
            int k = f >> 5, c4 = (f & 31) * 4;
            *(float4*)&Ws[k][c4] = *(const float4*)(Wh + (size_t)(k0 + k) * 128 + c4);
        }
        __syncthreads();
#pragma unroll
        for (int k = 0; k < 32; k += 2) {
            float4 wv0 = *(float4*)&Ws[k][lane * 4];
            float4 wv1 = *(float4*)&Ws[k + 1][lane * 4];
#pragma unroll
            for (int r = 0; r < 8; r++) {
                float2 xv = *(float2*)&Xs[warp * 8 + r][k];
                acc[r].x = fmaf(xv.x, wv0.x, acc[r].x);
                acc[r].y = fmaf(xv.x, wv0.y, acc[r].y);
                acc[r].z = fmaf(xv.x, wv0.z, acc[r].z);
                acc[r].w = fmaf(xv.x, wv0.w, acc[r].w);
                acc[r].x = fmaf(xv.y, wv1.x, acc[r].x);
                acc[r].y = fmaf(xv.y, wv1.y, acc[r].y);
                acc[r].z = fmaf(xv.y, wv1.z, acc[r].z);
                acc[r].w = fmaf(xv.y, wv1.w, acc[r].w);
            }
        }
        __syncthreads();
    }

    // epilogue: bias + relu + store + fused attention-score dots
    float4 bias = *(const float4*)(b1 + h * 128 + lane * 4);
    float4 w2   = *(const float4*)(a2w + h * 128 + lane * 4);
    float4 w1a  = make_float4(0.f, 0.f, 0.f, 0.f);
    if (lvl == 0) w1a = *(const float4*)(a1w + h * 128 + lane * 4);

    float* a2out = (lvl == 0) ? (g_a20 + h * CN0)
                 : (lvl == 1) ? (g_a21 + h * CN1)
                              : (g_a22 + h * CN2);
    const float a2bias = a2b[h];
    const float a1bias = a1b[h];

#pragma unroll
    for (int r = 0; r < 8; r++) {
        int gr = row0 + warp * 8 + r;
        float4 v;
        v.x = fmaxf(acc[r].x + bias.x, 0.f);
        v.y = fmaxf(acc[r].y + bias.y, 0.f);
        v.z = fmaxf(acc[r].z + bias.z, 0.f);
        v.w = fmaxf(acc[r].w + bias.w, 0.f);
        if (gr < Nl) *(float4*)(out + (size_t)gr * ldo + lane * 4) = v;

        float s2 = v.x * w2.x + v.y * w2.y + v.z * w2.z + v.w * w2.w;
#pragma unroll
        for (int o = 16; o; o >>= 1) s2 += __shfl_xor_sync(0xffffffffu, s2, o);
        if (lane == 0 && gr < Nl) a2out[gr] = s2 + a2bias;

        if (lvl == 0) {
            float s1 = v.x * w1a.x + v.y * w1a.y + v.z * w1a.z + v.w * w1a.w;
#pragma unroll
            for (int o = 16; o; o >>= 1) s1 += __shfl_xor_sync(0xffffffffu, s1, o);
            if (lane == 0 && gr < Nl) g_a1[h * CN0 + gr] = s1 + a1bias;
        }
    }
}

// ---------------- bucket build: per-row edge lists (one thread per nnz) ----------------
__global__ void bucket_kernel(
    const int* __restrict__ rows0, const int* __restrict__ cols0,
    const int* __restrict__ rows1, const int* __restrict__ cols1,
    const int* __restrict__ rows2, const int* __restrict__ cols2)
{
    int i = blockIdx.x * blockDim.x + threadIdx.x;
    int lvl, e;
    const int *rows, *cols;
    if (i < NNZ0)                { lvl = 0; e = i;               rows = rows0; cols = cols0; }
    else if (i < NNZ0 + NNZ1)    { lvl = 1; e = i - NNZ0;        rows = rows1; cols = cols1; }
    else if (i < NNZ0 + NNZ1 + NNZ2) { lvl = 2; e = i - NNZ0 - NNZ1; rows = rows2; cols = cols2; }
    else return;
    int r = rows[e], c = cols[e];
    int pos = atomicAdd(&g_cnt[lvl * CN0 + r], 1);
    if (pos < CAP) g_list[(size_t)(lvl * CN0 + r) * CAP + pos] = c;
}

// ---------------- attention gather: one warp per (row, head, level) ----------------
__global__ __launch_bounds__(256) void agg_kernel()
{
    int w = (blockIdx.x * blockDim.x + threadIdx.x) >> 5;
    int lane = threadIdx.x & 31;
    if (w >= 3 * HEADS * CN0) return;
    int lvl = w / (HEADS * CN0);
    int rem = w - lvl * (HEADS * CN0);
    int h   = rem / CN0;
    int row = rem - h * CN0;

    int n = g_cnt[lvl * CN0 + row];
    if (n > CAP) n = CAP;
    float a1v = g_a1[h * CN0 + row];

    const float* a2p; const float* yb; int ldy;
    if (lvl == 0)      { a2p = g_a20 + h * CN0; yb = g_cat + (size_t)h * CN0 * 512; ldy = 512; }
    else if (lvl == 1) { a2p = g_a21 + h * CN1; yb = g_y1  + (size_t)h * CN1 * 128; ldy = 128; }
    else               { a2p = g_a22 + h * CN2; yb = g_y2  + (size_t)h * CN2 * 128; ldy = 128; }

    const int* lst = g_list + (size_t)(lvl * CN0 + row) * CAP;
    float4 acc = make_float4(0.f, 0.f, 0.f, 0.f);
    for (int j = 0; j < n; j++) {
        int c = lst[j];                       // broadcast load
        float z = a1v + a2p[c];               // broadcast load
        float att = 1.f / (1.f + __expf(-z));
        float4 yv = *(const float4*)(yb + (size_t)c * ldy + lane * 4);
        acc.x = fmaf(att, yv.x, acc.x);
        acc.y = fmaf(att, yv.y, acc.y);
        acc.z = fmaf(att, yv.z, acc.z);
        acc.w = fmaf(att, yv.w, acc.w);
    }
    *(float4*)(g_cat + (size_t)h * CN0 * 512 + (size_t)row * 512 + 128 + lvl * 128 + lane * 4) = acc;
}

// ---------------- GEMM2: out = mean_h(cat_h @ Wagg_h + bagg_h) ----------------
__global__ __launch_bounds__(256) void gemm2_kernel(
    const float* __restrict__ Wagg, const float* __restrict__ bagg,
    float* __restrict__ out)
{
    const int row0 = blockIdx.x * 64;
    __shared__ float Xs[64][32];
    __shared__ float Ws[32][128];

    const int tid  = threadIdx.x;
    const int lane = tid & 31;
    const int warp = tid >> 5;

    float4 acc[8];
#pragma unroll
    for (int r = 0; r < 8; r++) acc[r] = make_float4(0.f, 0.f, 0.f, 0.f);

    for (int h = 0; h < HEADS; h++) {
        const float* A  = g_cat + (size_t)h * CN0 * 512;
        const float* Wh = Wagg + (size_t)h * 512 * 128;
        for (int k0 = 0; k0 < 512; k0 += 32) {
#pragma unroll
            for (int i = 0; i < 2; i++) {
                int f = tid * 2 + i;
                int r = f >> 3, kk = (f & 7) * 4;
                float4 v = make_float4(0.f, 0.f, 0.f, 0.f);
                int gr = row0 + r;
                if (gr < CN0) v = *(const float4*)(A + (size_t)gr * 512 + k0 + kk);
                *(float4*)&Xs[r][kk] = v;
            }
#pragma unroll
            for (int i = 0; i < 4; i++) {
                int f = tid + i * 256;
                int k = f >> 5, c4 = (f & 31) * 4;
                *(float4*)&Ws[k][c4] = *(const float4*)(Wh + (size_t)(k0 + k) * 128 + c4);
            }
            __syncthreads();
#pragma unroll
            for (int k = 0; k < 32; k += 2) {
                float4 wv0 = *(float4*)&Ws[k][lane * 4];
                float4 wv1 = *(float4*)&Ws[k + 1][lane * 4];
#pragma unroll
                for (int r = 0; r < 8; r++) {
                    float2 xv = *(float2*)&Xs[warp * 8 + r][k];
                    acc[r].x = fmaf(xv.x, wv0.x, acc[r].x);
                    acc[r].y = fmaf(xv.x, wv0.y, acc[r].y);
                    acc[r].z = fmaf(xv.x, wv0.z, acc[r].z);
                    acc[r].w = fmaf(xv.x, wv0.w, acc[r].w);
                    acc[r].x = fmaf(xv.y, wv1.x, acc[r].x);
                    acc[r].y = fmaf(xv.y, wv1.y, acc[r].y);
                    acc[r].z = fmaf(xv.y, wv1.z, acc[r].z);
                    acc[r].w = fmaf(xv.y, wv1.w, acc[r].w);
                }
            }
            __syncthreads();
        }
    }

    // epilogue: + sum_h bagg, * 1/4
    float4 bsum = make_float4(0.f, 0.f, 0.f, 0.f);
#pragma unroll
    for (int h = 0; h < HEADS; h++) {
        float4 bg = *(const float4*)(bagg + h * 128 + lane * 4);
        bsum.x += bg.x; bsum.y += bg.y; bsum.z += bg.z; bsum.w += bg.w;
    }
#pragma unroll
    for (int r = 0; r < 8; r++) {
        int gr = row0 + warp * 8 + r;
        if (gr < CN0) {
            float4 v;
            v.x = (acc[r].x + bsum.x) * 0.25f;
            v.y = (acc[r].y + bsum.y) * 0.25f;
            v.z = (acc[r].z + bsum.z) * 0.25f;
            v.w = (acc[r].w + bsum.w) * 0.25f;
            *(float4*)(out + (size_t)gr * 128 + lane * 4) = v;
        }
    }
}

// ---------------- launch ----------------
extern "C" void kernel_launch(void* const* d_in, const int* in_sizes, int n_in,
                              void* d_out, int out_size)
{
    const float* x0    = (const float*)d_in[0];
    const float* x1    = (const float*)d_in[1];
    const float* x2    = (const float*)d_in[2];
    const int*   rows0 = (const int*)d_in[3];
    const int*   cols0 = (const int*)d_in[4];
    const int*   rows1 = (const int*)d_in[5];
    const int*   cols1 = (const int*)d_in[6];
    const int*   rows2 = (const int*)d_in[7];
    const int*   cols2 = (const int*)d_in[8];
    const float* W1    = (const float*)d_in[9];
    const float* b1    = (const float*)d_in[10];
    const float* a1w   = (const float*)d_in[11];
    const float* a1b   = (const float*)d_in[12];
    const float* a2w   = (const float*)d_in[13];
    const float* a2b   = (const float*)d_in[14];
    const float* Wagg  = (const float*)d_in[15];
    const float* bagg  = (const float*)d_in[16];
    float* out = (float*)d_out;

    // 1. zero bucket counters
    zero_cnt_kernel<<<(3 * CN0 + 255) / 256, 256>>>();

    // 2. Linear1 + ReLU + attention dots (all levels, all heads)
    {
        dim3 grid((CN1 + 63) / 64, 3, HEADS);   // max rowblocks over levels
        gemm1_kernel<<<grid, 256>>>(x0, x1, x2, W1, b1, a1w, a1b, a2w, a2b);
    }

    // 3. build per-row bucket lists
    bucket_kernel<<<(NNZ0 + NNZ1 + NNZ2 + 255) / 256, 256>>>(
        rows0, cols0, rows1, cols1, rows2, cols2);

    // 4. attention gather into cat buffer
    {
        int warps = 3 * HEADS * CN0;
        agg_kernel<<<(warps * 32 + 255) / 256, 256>>>();
    }

    // 5. aggregation GEMM + head mean
    gemm2_kernel<<<(CN0 + 63) / 64, 256>>>(Wagg, bagg, out);
}